// round 5
// baseline (speedup 1.0000x reference)
#include <cuda_runtime.h>
#include <cuda_bf16.h>
#include <cstdint>

// Correlation1D band-GEMM: warp-specialized producer/consumer pipeline.
// Consumers (warps 0-5): m32 each, mma.sync bf16 3-pass fp32 emulation,
//   A-fragments built directly from fp32 stage (LDS + in-reg hi/lo split).
// Producers (warps 6-11): cp.async issue + B fp32->bf16(hi|lo) convert.
// out[b,d,h,w] = (1/256)*sum_c in1[b,c,h,w]*in2pad[b,c,h,w+d-40]

#define Bn 8
#define Cn 256
#define Hn 96
#define Wn 192
#define Dn 81
#define PADn 40
#define HWn (Hn * Wn)

#define NTHREADS 384
#define KC 16
#define NCHUNK (Cn / KC)          // 16
#define AROWS 192
#define BROWS 272

#define STA_ROWF 196              // fp32 A stage row floats (padded)
#define STB_ROWF 276              // fp32 B stage row floats (padded)
#define STA_BYTES (KC * STA_ROWF * 4)   // 12544
#define STB_BYTES (KC * STB_ROWF * 4)   // 17664

#define ROWB 64                   // bf16 B tile row: [hi 32B | lo 32B]
#define TB_BYTES (BROWS * ROWB)   // 17408

#define OFF_AST 0
#define OFF_BST (2 * STA_BYTES)                 // 25088
#define OFF_TB  (OFF_BST + 2 * STB_BYTES)       // 60416
#define SMEM_USED (OFF_TB + 2 * TB_BYTES)       // 95232
#define DYNSMEM (SMEM_USED + 1024)

#define SWX(row, koff) ((unsigned)(koff) ^ ((((unsigned)(row) >> 1) & 3u) << 4))

// named barriers: FULL_s = 1+s, FREE_s = 3+s, producer-internal = 5
#define BAR_SYNC_ALL(id)   asm volatile("bar.sync %0, 384;" :: "r"(id) : "memory")
#define BAR_ARRIVE_ALL(id) asm volatile("bar.arrive %0, 384;" :: "r"(id) : "memory")
#define BAR_SYNC_PROD()    asm volatile("bar.sync 5, 192;" ::: "memory")

static __device__ __forceinline__ uint32_t smem_u32(const void* p) {
    uint32_t a;
    asm("{ .reg .u64 t; cvta.to.shared.u64 t, %1; cvt.u32.u64 %0, t; }" : "=r"(a) : "l"(p));
    return a;
}

static __device__ __forceinline__ void cp_async16(uint32_t dst, const void* src) {
    asm volatile("cp.async.cg.shared.global [%0], [%1], 16;" :: "r"(dst), "l"(src) : "memory");
}

static __device__ __forceinline__ void cvt8_store(char* tile, int row, int g,
                                                  const float* v) {
    unsigned hu[4], lu[4];
#pragma unroll
    for (int k = 0; k < 4; ++k) {
        __nv_bfloat16 h0 = __float2bfloat16(v[2 * k]);
        __nv_bfloat16 h1 = __float2bfloat16(v[2 * k + 1]);
        __nv_bfloat16 l0 = __float2bfloat16(v[2 * k] - __bfloat162float(h0));
        __nv_bfloat16 l1 = __float2bfloat16(v[2 * k + 1] - __bfloat162float(h1));
        hu[k] = (unsigned)__bfloat16_as_ushort(h0) | ((unsigned)__bfloat16_as_ushort(h1) << 16);
        lu[k] = (unsigned)__bfloat16_as_ushort(l0) | ((unsigned)__bfloat16_as_ushort(l1) << 16);
    }
    char* rowp = tile + row * ROWB;
    *(uint4*)(rowp + SWX(row, 16 * g)) = make_uint4(hu[0], hu[1], hu[2], hu[3]);
    *(uint4*)(rowp + SWX(row, 32 + 16 * g)) = make_uint4(lu[0], lu[1], lu[2], lu[3]);
}

#define MMA_BF16(a4, A, b0, b1)                                                \
    asm volatile("mma.sync.aligned.m16n8k16.row.col.f32.bf16.bf16.f32 "        \
        "{%0,%1,%2,%3}, {%4,%5,%6,%7}, {%8,%9}, {%0,%1,%2,%3};"                \
        : "+f"((a4)[0]), "+f"((a4)[1]), "+f"((a4)[2]), "+f"((a4)[3])           \
        : "r"((A)[0]), "r"((A)[1]), "r"((A)[2]), "r"((A)[3]), "r"(b0), "r"(b1))

__global__ __launch_bounds__(NTHREADS, 1)
void corr1d_ws_kernel(const float* __restrict__ in1,
                      const float* __restrict__ in2,
                      float* __restrict__ out) {
    extern __shared__ char dsm_raw[];
    const uint32_t dsm_addr = smem_u32(dsm_raw);
    const uint32_t base_u = (dsm_addr + 1023u) & ~1023u;
    char* smp = dsm_raw + (base_u - dsm_addr);

    const int h = blockIdx.x;
    const int b = blockIdx.y;
    const int tid = threadIdx.x;
    const int wid = tid >> 5;
    const int lane = tid & 31;

    const float* a_src = in1 + (size_t)b * Cn * HWn + (size_t)h * Wn;
    const float* b_src = in2 + (size_t)b * Cn * HWn + (size_t)h * Wn;

    float acc[24][4];   // consumer accumulators (producers: dead)
#pragma unroll
    for (int n = 0; n < 24; ++n)
#pragma unroll
        for (int i = 0; i < 4; ++i) acc[n][i] = 0.0f;

    const int w0m = (wid < 6) ? wid * 32 : 0;

    if (wid >= 6) {
        // ================= PRODUCERS (warps 6-11) =================
        const int ptid = tid - 192;

        // one-time zero of OOB u-regions of both B stages (u<40, u>=232)
        for (int t = ptid; t < 2 * KC * 80; t += 192) {
            const int s = t / (KC * 80);
            const int r = (t % (KC * 80)) / 80;
            const int j = t % 80;
            const int u = (j < 40) ? j : (232 + j - 40);
            *(float*)(smp + OFF_BST + s * STB_BYTES + r * (STB_ROWF * 4) + 4 * u) = 0.0f;
        }
        BAR_SYNC_PROD();   // zeros visible among producers before first convert

        for (int i = 0; i < NCHUNK; ++i) {
            const int s = i & 1;
            BAR_SYNC_ALL(3 + s);              // buffer s free (consumers done i-2)

            const int c0 = i * KC;
            const uint32_t stA = base_u + OFF_AST + s * STA_BYTES;
            const uint32_t stB = base_u + OFF_BST + s * STB_BYTES;
#pragma unroll
            for (int j = 0; j < 8; ++j) {
                int op = ptid + j * 192;      // 0..1535
                if (op < 768) {
                    const int k = op / 48, q = op % 48;
                    cp_async16(stA + k * (STA_ROWF * 4) + q * 16,
                               a_src + (size_t)(c0 + k) * HWn + 4 * q);
                } else {
                    op -= 768;
                    const int k = op / 48, q = op % 48;
                    cp_async16(stB + k * (STB_ROWF * 4) + 160 + q * 16,
                               b_src + (size_t)(c0 + k) * HWn + 4 * q);
                }
            }
            asm volatile("cp.async.commit_group;" ::: "memory");
            asm volatile("cp.async.wait_group 0;" ::: "memory");
            BAR_SYNC_PROD();                  // cross-producer cp.async visibility

            // convert B fp32 -> bf16 hi|lo tile
            char* tb = smp + OFF_TB + s * TB_BYTES;
            const char* sb = smp + OFF_BST + s * STB_BYTES;
            for (int t = ptid; t < BROWS * 2; t += 192) {
                const int u = t % BROWS;
                const int g = t / BROWS;
                float v[8];
#pragma unroll
                for (int j = 0; j < 8; ++j)
                    v[j] = *(const float*)(sb + (8 * g + j) * (STB_ROWF * 4) + 4 * u);
                cvt8_store(tb, u, g, v);
            }
            __threadfence_block();
            BAR_ARRIVE_ALL(1 + s);            // buffer s full
        }
    } else {
        // ================= CONSUMERS (warps 0-5), m32 each =================
        const int b_rowoff = (lane & 7) + ((lane >> 4) & 1) * 8;
        const int b_k16 = ((lane >> 3) & 1) * 16;
        const int k0 = (lane & 3) * 2;
        const int wa = w0m + (lane >> 2);

        BAR_ARRIVE_ALL(3);   // buffers initially free
        BAR_ARRIVE_ALL(4);

        for (int i = 0; i < NCHUNK; ++i) {
            const int s = i & 1;
            BAR_SYNC_ALL(1 + s);              // buffer s full

            const char* sa = smp + OFF_AST + s * STA_BYTES;
            const uint32_t tb_u = base_u + OFF_TB + s * TB_BYTES;

            // A fragments for both m-tiles, hi and lo, direct from fp32 stage
            uint32_t AH[2][4], AL[2][4];
#pragma unroll
            for (int mt = 0; mt < 2; ++mt) {
#pragma unroll
                for (int q = 0; q < 4; ++q) {
                    const int kk = k0 + (q >> 1) * 8;
                    const int ww = wa + 16 * mt + (q & 1) * 8;
                    const float f0 = *(const float*)(sa + kk * (STA_ROWF * 4) + 4 * ww);
                    const float f1 = *(const float*)(sa + (kk + 1) * (STA_ROWF * 4) + 4 * ww);
                    __nv_bfloat162 hh = __floats2bfloat162_rn(f0, f1);
                    const float r0 = f0 - __bfloat162float(hh.x);
                    const float r1 = f1 - __bfloat162float(hh.y);
                    __nv_bfloat162 ll = __floats2bfloat162_rn(r0, r1);
                    AH[mt][q] = *(uint32_t*)&hh;
                    AL[mt][q] = *(uint32_t*)&ll;
                }
            }

#pragma unroll
            for (int pos = 0; pos < 7; ++pos) {
                const int ub = w0m + pos * 16 + b_rowoff;
                uint32_t bh[4], bl[4];
                {
                    const uint32_t addr = tb_u + ub * ROWB + SWX(ub, b_k16);
                    asm volatile("ldmatrix.sync.aligned.m8n8.x4.shared.b16 {%0,%1,%2,%3}, [%4];"
                                 : "=r"(bh[0]), "=r"(bh[1]), "=r"(bh[2]), "=r"(bh[3]) : "r"(addr));
                }
                {
                    const uint32_t addr = tb_u + ub * ROWB + SWX(ub, 32 + b_k16);
                    asm volatile("ldmatrix.sync.aligned.m8n8.x4.shared.b16 {%0,%1,%2,%3}, [%4];"
                                 : "=r"(bl[0]), "=r"(bl[1]), "=r"(bl[2]), "=r"(bl[3]) : "r"(addr));
                }
#pragma unroll
                for (int t2 = 0; t2 < 2; ++t2) {
                    const int jn = pos * 2 + t2;
                    const uint32_t b0h = bh[2 * t2], b1h = bh[2 * t2 + 1];
                    const uint32_t b0l = bl[2 * t2], b1l = bl[2 * t2 + 1];
#pragma unroll
                    for (int mt = 0; mt < 2; ++mt) {
                        if (jn >= 2 * mt && jn < 12 + 2 * mt) {
                            const int ai = mt ? (12 + jn - 2) : jn;
                            MMA_BF16(acc[ai], AH[mt], b0h, b1h);
                            MMA_BF16(acc[ai], AH[mt], b0l, b1l);
                            MMA_BF16(acc[ai], AL[mt], b0h, b1h);
                        }
                    }
                }
            }
            if (i < NCHUNK - 2) BAR_ARRIVE_ALL(3 + s);   // buffer s free
        }
    }

    __syncthreads();

    // ---- epilogue: band extraction into smem, then coalesced store ----
    float* outT = (float*)smp;  // [81][192] f32
    if (wid < 6) {
        const float scale = 1.0f / (float)Cn;
        const int r_ = lane >> 2;
        const int col2 = (lane & 3) * 2;
#pragma unroll
        for (int ai = 0; ai < 24; ++ai) {
            const int mt = ai / 12;
            const int jn = (ai < 12) ? ai : (ai - 10);
#pragma unroll
            for (int half = 0; half < 2; ++half) {
                const int mrow = 16 * mt + r_ + half * 8;
                const int w = w0m + mrow;
#pragma unroll
                for (int e = 0; e < 2; ++e) {
                    const int d = 8 * jn + col2 + e - mrow;
                    if (d >= 0 && d < Dn) {
                        outT[d * Wn + w] = acc[ai][half * 2 + e] * scale;
                    }
                }
            }
        }
    }
    __syncthreads();

    for (int t = tid; t < Dn * (Wn / 4); t += NTHREADS) {
        const int d = t / (Wn / 4);
        const int q = t % (Wn / 4);
        const float4 v = ((const float4*)outT)[d * (Wn / 4) + q];
        *(float4*)(out + (((size_t)b * Dn + d) * Hn + h) * Wn + q * 4) = v;
    }
}

extern "C" void kernel_launch(void* const* d_in, const int* in_sizes, int n_in,
                              void* d_out, int out_size) {
    const float* in1 = (const float*)d_in[0];
    const float* in2 = (const float*)d_in[1];
    float* out = (float*)d_out;
    cudaFuncSetAttribute(corr1d_ws_kernel, cudaFuncAttributeMaxDynamicSharedMemorySize, DYNSMEM);
    dim3 grid(Hn, Bn);   // (96, 8)
    corr1d_ws_kernel<<<grid, NTHREADS, DYNSMEM>>>(in1, in2, out);
}

// round 6
// speedup vs baseline: 1.1516x; 1.1516x over previous
#include <cuda_runtime.h>
#include <cuda_bf16.h>
#include <cstdint>

// Correlation1D band-GEMM, homogeneous-warp software pipeline:
//  - per chunk (KC=8 channels): one __syncthreads
//  - chunk i+2 fp32 prefetched into REGISTERS (ldcg) while computing chunk i
//  - convert+STS of chunk i+1 overlaps other warps' compute via natural stagger
//  - mma.sync.m16n8k8 bf16, 3-pass (hh, hl, lh) fp32 emulation
// out[b,d,h,w] = (1/256)*sum_c in1[b,c,h,w]*in2pad[b,c,h,w+d-40]
// in1,in2 [8,256,96,192] f32; out [8,81,96,192] f32.

#define Bn 8
#define Cn 256
#define Hn 96
#define Wn 192
#define Dn 81
#define PADn 40
#define HWn (Hn * Wn)

#define NTHREADS 384
#define KC 8
#define NCHUNK (Cn / KC)          // 32
#define AROWS 192
#define BROWS 272

#define ROWB 32                   // tile row: [hi 8ch = 16B | lo 16B]
#define TAB (AROWS * ROWB)        // 6144
#define TBB (BROWS * ROWB)        // 8704
#define BUFB (TAB + TBB)          // 14848 (128B-aligned)
#define DYNSMEM 63232             // max(2*BUFB=29696, outT 81*192*4=62208) + align

// per-row XOR swizzle for 32B rows, 16B granularity: 8-row LDSM phases conflict-free
#define SWX8(row, koff) ((unsigned)(koff) ^ ((((unsigned)(row) >> 2) & 1u) << 4))

static __device__ __forceinline__ uint32_t smem_u32(const void* p) {
    uint32_t a;
    asm("{ .reg .u64 t; cvta.to.shared.u64 t, %1; cvt.u32.u64 %0, t; }" : "=r"(a) : "l"(p));
    return a;
}

#define MMA_K8(a4, A0, A1, B0)                                                 \
    asm volatile("mma.sync.aligned.m16n8k8.row.col.f32.bf16.bf16.f32 "         \
        "{%0,%1,%2,%3}, {%4,%5}, {%6}, {%0,%1,%2,%3};"                         \
        : "+f"((a4)[0]), "+f"((a4)[1]), "+f"((a4)[2]), "+f"((a4)[3])           \
        : "r"(A0), "r"(A1), "r"(B0))

#define LDSM_X4(r0, r1, r2, r3, addr)                                          \
    asm volatile("ldmatrix.sync.aligned.m8n8.x4.shared.b16 {%0,%1,%2,%3}, [%4];" \
        : "=r"(r0), "=r"(r1), "=r"(r2), "=r"(r3) : "r"(addr))

__global__ __launch_bounds__(NTHREADS, 2)
void corr1d_sp_kernel(const float* __restrict__ in1,
                      const float* __restrict__ in2,
                      float* __restrict__ out) {
    extern __shared__ char dsm_raw[];
    const uint32_t dsm_addr = smem_u32(dsm_raw);
    const uint32_t base_u = (dsm_addr + 1023u) & ~1023u;
    char* smp = dsm_raw + (base_u - dsm_addr);

    const int h = blockIdx.x;
    const int b = blockIdx.y;
    const int tid = threadIdx.x;
    const int wid = tid >> 5;
    const int lane = tid & 31;

    // ---- per-thread producer role: threads 0-191 load A row w=tid,
    //      threads 192-383 load B col=tid-192 (tile row u=col+40) ----
    const bool isA = (tid < 192);
    const int col = isA ? tid : (tid - 192);
    const int trow = isA ? col : (col + PADn);
    const int tile_off = isA ? 0 : TAB;
    const float* gsrc = (isA ? in1 : in2) +
                        (size_t)b * Cn * HWn + (size_t)h * Wn + col;

    // ---- zero B-tile pad rows (u<40, u>=232) in both buffers, once ----
    for (int t = tid; t < 2 * 80 * 2; t += NTHREADS) {
        const int buf = t / 160;
        const int r = (t % 160) / 2;
        const int j = t % 2;
        const int u = (r < 40) ? r : (232 + r - 40);
        ((uint4*)(smp + buf * BUFB + TAB + u * ROWB))[j] = make_uint4(0, 0, 0, 0);
    }

    float acc[12][4];
#pragma unroll
    for (int n = 0; n < 12; ++n)
#pragma unroll
        for (int i = 0; i < 4; ++i) acc[n][i] = 0.0f;

    // ---- precomputed LDSM address offsets (within a tile buffer) ----
    const int w0 = wid * 16;
    const int a_row = w0 + (lane & 15);
    const unsigned a_off = TAB * 0 + a_row * ROWB + SWX8(a_row, (lane >> 4) * 16);
    unsigned bh_off[3], bl_off[3];
#pragma unroll
    for (int q = 0; q < 3; ++q) {
        const int br = w0 + 32 * q + lane;
        bh_off[q] = TAB + br * ROWB + SWX8(br, 0);
        bl_off[q] = TAB + br * ROWB + SWX8(br, 16);
    }

    float pf[8];
    // load chunk ch's 8 channel-values into pf
    auto loadc = [&](int ch) {
        const size_t o = (size_t)ch * KC * HWn;
#pragma unroll
        for (int j = 0; j < 8; ++j)
            pf[j] = __ldcg(gsrc + o + (size_t)j * HWn);
    };
    // convert pf -> bf16 hi|lo and store to tile buffer `buf`
    auto cvst = [&](int buf) {
        unsigned hu[4], lu[4];
#pragma unroll
        for (int k = 0; k < 4; ++k) {
            __nv_bfloat162 hh = __floats2bfloat162_rn(pf[2 * k], pf[2 * k + 1]);
            const float r0 = pf[2 * k] - __bfloat162float(hh.x);
            const float r1 = pf[2 * k + 1] - __bfloat162float(hh.y);
            __nv_bfloat162 ll = __floats2bfloat162_rn(r0, r1);
            hu[k] = *(unsigned*)&hh;
            lu[k] = *(unsigned*)&ll;
        }
        char* rowp = smp + buf * BUFB + tile_off + trow * ROWB;
        *(uint4*)(rowp + SWX8(trow, 0)) = make_uint4(hu[0], hu[1], hu[2], hu[3]);
        *(uint4*)(rowp + SWX8(trow, 16)) = make_uint4(lu[0], lu[1], lu[2], lu[3]);
    };

    // ---- prologue ----
    loadc(0);
    cvst(0);
    loadc(1);
    __syncthreads();   // tiles[0] ready (also covers pad zeros)

    // ---- main pipeline: one sync per chunk ----
    for (int i = 0; i < NCHUNK; ++i) {
        const uint32_t tb = base_u + (i & 1) * BUFB;

        // compute chunk i from tiles[i&1] (hides chunk i+1's in-flight LDGs)
        uint32_t af0, af1, af2, af3;
        LDSM_X4(af0, af1, af2, af3, tb + a_off);   // hi a0,a1 | lo a0,a1
#pragma unroll
        for (int q = 0; q < 3; ++q) {
            uint32_t bh0, bh1, bh2, bh3, bl0, bl1, bl2, bl3;
            LDSM_X4(bh0, bh1, bh2, bh3, tb + bh_off[q]);
            LDSM_X4(bl0, bl1, bl2, bl3, tb + bl_off[q]);
            uint32_t bhv[4] = {bh0, bh1, bh2, bh3};
            uint32_t blv[4] = {bl0, bl1, bl2, bl3};
#pragma unroll
            for (int t = 0; t < 4; ++t) {
                float* a4 = acc[4 * q + t];
                MMA_K8(a4, af0, af1, bhv[t]);   // hh
                MMA_K8(a4, af0, af1, blv[t]);   // hl
                MMA_K8(a4, af2, af3, bhv[t]);   // lh
            }
        }

        // stage chunk i+1 into the other tile buffer; prefetch chunk i+2
        if (i + 1 < NCHUNK) {
            cvst((i + 1) & 1);
            if (i + 2 < NCHUNK) loadc(i + 2);
        }
        __syncthreads();
    }

    // ---- epilogue: band extraction into smem, then coalesced store ----
    float* outT = (float*)smp;  // [81][192] f32 over both tile buffers
    const float scale = 1.0f / (float)Cn;
    const int r_ = lane >> 2;
    const int col2 = (lane & 3) * 2;
#pragma unroll
    for (int nt = 0; nt < 12; ++nt) {
#pragma unroll
        for (int half = 0; half < 2; ++half) {
            const int mrow = r_ + half * 8;
            const int w = w0 + mrow;
#pragma unroll
            for (int e = 0; e < 2; ++e) {
                const int d = nt * 8 + col2 + e - mrow;
                if (d >= 0 && d < Dn) {
                    outT[d * Wn + w] = acc[nt][half * 2 + e] * scale;
                }
            }
        }
    }
    __syncthreads();

    for (int t = tid; t < Dn * (Wn / 4); t += NTHREADS) {
        const int d = t / (Wn / 4);
        const int q = t % (Wn / 4);
        const float4 v = ((const float4*)outT)[d * (Wn / 4) + q];
        *(float4*)(out + (((size_t)b * Dn + d) * Hn + h) * Wn + q * 4) = v;
    }
}

extern "C" void kernel_launch(void* const* d_in, const int* in_sizes, int n_in,
                              void* d_out, int out_size) {
    const float* in1 = (const float*)d_in[0];
    const float* in2 = (const float*)d_in[1];
    float* out = (float*)d_out;
    cudaFuncSetAttribute(corr1d_sp_kernel, cudaFuncAttributeMaxDynamicSharedMemorySize, DYNSMEM);
    dim3 grid(Hn, Bn);   // (96, 8)
    corr1d_sp_kernel<<<grid, NTHREADS, DYNSMEM>>>(in1, in2, out);
}

// round 8
// speedup vs baseline: 1.6290x; 1.4145x over previous
#include <cuda_runtime.h>
#include <cuda_bf16.h>
#include <cstdint>

// Correlation1D band-GEMM: k16 bf16 3-pass fp32 emulation.
// One __syncthreads per 16-channel chunk; cp.async double-buffered fp32 stages;
// B converted to bf16 hi|lo tile (double-buffered); A fragments built directly
// from the fp32 stage in registers (no A tile).
// R8 = R7 with the cp.async wait fixed (wait_group 0 — the single in-flight
// group must be complete before the next iteration reads its stage buffer).
// out[b,d,h,w] = (1/256)*sum_c in1[b,c,h,w]*in2pad[b,c,h,w+d-40]

#define Bn 8
#define Cn 256
#define Hn 96
#define Wn 192
#define Dn 81
#define PADn 40
#define HWn (Hn * Wn)

#define NTHREADS 384
#define KC 16
#define NCHUNK (Cn / KC)          // 16
#define BROWS 272

#define STROWF 196                // fp32 stage row floats (192 used, pad for banks)
#define STBYTES (KC * STROWF * 4) // 12544

#define ROWB 64                   // tileB row: [hi 16ch = 32B | lo 32B]
#define TBB (BROWS * ROWB)        // 17408

#define OFF_SA0 0
#define OFF_SA1 STBYTES
#define OFF_SB0 (2 * STBYTES)
#define OFF_SB1 (3 * STBYTES)
#define OFF_TB0 (4 * STBYTES)               // 50176
#define OFF_TB1 (OFF_TB0 + TBB)             // 67584
#define SMEM_USED (OFF_TB1 + TBB)           // 84992
#define DYNSMEM (SMEM_USED + 1024)

#define SWX(row, koff) ((unsigned)(koff) ^ ((((unsigned)(row) >> 1) & 3u) << 4))

static __device__ __forceinline__ uint32_t smem_u32(const void* p) {
    uint32_t a;
    asm("{ .reg .u64 t; cvta.to.shared.u64 t, %1; cvt.u32.u64 %0, t; }" : "=r"(a) : "l"(p));
    return a;
}

static __device__ __forceinline__ void cp_async16(uint32_t dst, const void* src) {
    asm volatile("cp.async.cg.shared.global [%0], [%1], 16;" :: "r"(dst), "l"(src) : "memory");
}

#define MMA_BF16(a4, A, b0, b1)                                                \
    asm volatile("mma.sync.aligned.m16n8k16.row.col.f32.bf16.bf16.f32 "        \
        "{%0,%1,%2,%3}, {%4,%5,%6,%7}, {%8,%9}, {%0,%1,%2,%3};"                \
        : "+f"((a4)[0]), "+f"((a4)[1]), "+f"((a4)[2]), "+f"((a4)[3])           \
        : "r"((A)[0]), "r"((A)[1]), "r"((A)[2]), "r"((A)[3]), "r"(b0), "r"(b1))

#define LDSM_X4(r, addr)                                                       \
    asm volatile("ldmatrix.sync.aligned.m8n8.x4.shared.b16 {%0,%1,%2,%3}, [%4];" \
        : "=r"((r)[0]), "=r"((r)[1]), "=r"((r)[2]), "=r"((r)[3]) : "r"(addr))

__global__ __launch_bounds__(NTHREADS, 2)
void corr1d_p3_kernel(const float* __restrict__ in1,
                      const float* __restrict__ in2,
                      float* __restrict__ out) {
    extern __shared__ char dsm_raw[];
    const uint32_t dsm_addr = smem_u32(dsm_raw);
    const uint32_t base_u = (dsm_addr + 1023u) & ~1023u;
    char* smp = dsm_raw + (base_u - dsm_addr);

    const int h = blockIdx.x;
    const int b = blockIdx.y;
    const int tid = threadIdx.x;
    const int wid = tid >> 5;
    const int lane = tid & 31;

    const float* a_src = in1 + (size_t)b * Cn * HWn + (size_t)h * Wn;
    const float* b_src = in2 + (size_t)b * Cn * HWn + (size_t)h * Wn;

    // ---- zero tileB pad rows (u<40, u>=232) in both buffers, once ----
    for (int t = tid; t < 2 * 80 * 4; t += NTHREADS) {
        const int buf = t / 320;
        const int r = (t % 320) / 4;
        const int j = t % 4;
        const int u = (r < 40) ? r : (232 + r - 40);
        ((uint4*)(smp + (buf ? OFF_TB1 : OFF_TB0) + u * ROWB))[j] = make_uint4(0, 0, 0, 0);
    }

    float acc[12][4];
#pragma unroll
    for (int n = 0; n < 12; ++n)
#pragma unroll
        for (int i = 0; i < 4; ++i) acc[n][i] = 0.0f;

    // convert-task constants (one task/thread): col 0..191, group g in {0,1}
    const int cv_col = tid % 192;
    const int cv_g = tid / 192;
    const int cv_u = cv_col + PADn;

    // compute constants
    const int w0 = wid * 16;
    const int b_rowoff = (lane & 7) + ((lane >> 4) & 1) * 8;
    const int b_k16 = ((lane >> 3) & 1) * 16;
    // A-direct read pattern: q in 0..3 -> (ww, kk)
    const int ad_w = w0 + (lane >> 2);
    const int ad_k = (lane & 3) * 2;

    // issue all cp.async for chunk ch into stage slot s
    auto issue = [&](int ch, int s) {
        const int c0 = ch * KC;
        const uint32_t stA = base_u + (s ? OFF_SA1 : OFF_SA0);
        const uint32_t stB = base_u + (s ? OFF_SB1 : OFF_SB0);
#pragma unroll
        for (int j = 0; j < 4; ++j) {
            int op = tid + j * NTHREADS;        // 0..1535
            const bool isA = (op < 768);
            if (!isA) op -= 768;
            const int k = op / 48, q = op % 48;
            const uint32_t dst = (isA ? stA : stB) + k * (STROWF * 4) + q * 16;
            const float* src = (isA ? a_src : b_src) + (size_t)(c0 + k) * HWn + 4 * q;
            cp_async16(dst, src);
        }
        asm volatile("cp.async.commit_group;" ::: "memory");
    };

    uint32_t AH[4], AL[4];   // A fragments for the chunk to be computed next iter

    issue(0, 0);
    asm volatile("cp.async.wait_group 0;" ::: "memory");
    __syncthreads();   // stage(0) visible; tile pad zeros visible

    for (int i = 0; i < NCHUNK; ++i) {
        const int s = i & 1;
        if (i + 1 < NCHUNK) issue(i + 1, s ^ 1);

        // ---- convert B(i): stageB[s] -> tileB[s] ----
        {
            const char* sb = smp + (s ? OFF_SB1 : OFF_SB0);
            float v[8];
#pragma unroll
            for (int j = 0; j < 8; ++j)
                v[j] = *(const float*)(sb + (8 * cv_g + j) * (STROWF * 4) + 4 * cv_col);
            unsigned hu[4], lu[4];
#pragma unroll
            for (int k = 0; k < 4; ++k) {
                __nv_bfloat162 hh = __floats2bfloat162_rn(v[2 * k], v[2 * k + 1]);
                const float r0 = v[2 * k] - __bfloat162float(hh.x);
                const float r1 = v[2 * k + 1] - __bfloat162float(hh.y);
                __nv_bfloat162 ll = __floats2bfloat162_rn(r0, r1);
                hu[k] = *(unsigned*)&hh;
                lu[k] = *(unsigned*)&ll;
            }
            char* rowp = smp + (s ? OFF_TB1 : OFF_TB0) + cv_u * ROWB;
            *(uint4*)(rowp + SWX(cv_u, 16 * cv_g)) = make_uint4(hu[0], hu[1], hu[2], hu[3]);
            *(uint4*)(rowp + SWX(cv_u, 32 + 16 * cv_g)) = make_uint4(lu[0], lu[1], lu[2], lu[3]);
        }

        // ---- compute chunk i-1 from tileB[s^1] with A frags built last iter ----
        if (i > 0) {
            const uint32_t tb = base_u + ((s ^ 1) ? OFF_TB1 : OFF_TB0);
#pragma unroll
            for (int ntp = 0; ntp < 6; ++ntp) {
                const int ub = w0 + ntp * 16 + b_rowoff;
                uint32_t bh[4], bl[4];
                LDSM_X4(bh, tb + ub * ROWB + SWX(ub, b_k16));
                LDSM_X4(bl, tb + ub * ROWB + SWX(ub, 32 + b_k16));
#pragma unroll
                for (int t2 = 0; t2 < 2; ++t2) {
                    float* a4 = acc[ntp * 2 + t2];
                    MMA_BF16(a4, AH, bh[2 * t2], bh[2 * t2 + 1]);
                    MMA_BF16(a4, AH, bl[2 * t2], bl[2 * t2 + 1]);
                    MMA_BF16(a4, AL, bh[2 * t2], bh[2 * t2 + 1]);
                }
            }
        }

        // ---- build A fragments for chunk i directly from stageA[s] ----
        {
            const char* sa = smp + (s ? OFF_SA1 : OFF_SA0);
#pragma unroll
            for (int q = 0; q < 4; ++q) {
                const int ww = ad_w + (q & 1) * 8;
                const int kk = ad_k + (q >> 1) * 8;
                const float f0 = *(const float*)(sa + kk * (STROWF * 4) + 4 * ww);
                const float f1 = *(const float*)(sa + (kk + 1) * (STROWF * 4) + 4 * ww);
                __nv_bfloat162 hh = __floats2bfloat162_rn(f0, f1);
                const float r0 = f0 - __bfloat162float(hh.x);
                const float r1 = f1 - __bfloat162float(hh.y);
                __nv_bfloat162 ll = __floats2bfloat162_rn(r0, r1);
                AH[q] = *(uint32_t*)&hh;
                AL[q] = *(uint32_t*)&ll;
            }
        }

        // single in-flight group: it must be COMPLETE before next iter reads it
        asm volatile("cp.async.wait_group 0;" ::: "memory");
        __syncthreads();   // stage(i+1) + tileB[s] visible; stage[s] reads done
    }

    // ---- tail: compute chunk NCHUNK-1 from tileB[(NCHUNK-1)&1] ----
    {
        const uint32_t tb = base_u + (((NCHUNK - 1) & 1) ? OFF_TB1 : OFF_TB0);
#pragma unroll
        for (int ntp = 0; ntp < 6; ++ntp) {
            const int ub = w0 + ntp * 16 + b_rowoff;
            uint32_t bh[4], bl[4];
            LDSM_X4(bh, tb + ub * ROWB + SWX(ub, b_k16));
            LDSM_X4(bl, tb + ub * ROWB + SWX(ub, 32 + b_k16));
#pragma unroll
            for (int t2 = 0; t2 < 2; ++t2) {
                float* a4 = acc[ntp * 2 + t2];
                MMA_BF16(a4, AH, bh[2 * t2], bh[2 * t2 + 1]);
                MMA_BF16(a4, AH, bl[2 * t2], bl[2 * t2 + 1]);
                MMA_BF16(a4, AL, bh[2 * t2], bh[2 * t2 + 1]);
            }
        }
    }
    __syncthreads();

    // ---- epilogue: band extraction into smem, then coalesced store ----
    float* outT = (float*)smp;  // [81][192] f32
    const float scale = 1.0f / (float)Cn;
    const int r_ = lane >> 2;
    const int col2 = (lane & 3) * 2;
#pragma unroll
    for (int nt = 0; nt < 12; ++nt) {
#pragma unroll
        for (int half = 0; half < 2; ++half) {
            const int mrow = r_ + half * 8;
            const int w = w0 + mrow;
#pragma unroll
            for (int e = 0; e < 2; ++e) {
                const int d = nt * 8 + col2 + e - mrow;
                if (d >= 0 && d < Dn) {
                    outT[d * Wn + w] = acc[nt][half * 2 + e] * scale;
                }
            }
        }
    }
    __syncthreads();

    for (int t = tid; t < Dn * (Wn / 4); t += NTHREADS) {
        const int d = t / (Wn / 4);
        const int q = t % (Wn / 4);
        const float4 v = ((const float4*)outT)[d * (Wn / 4) + q];
        *(float4*)(out + (((size_t)b * Dn + d) * Hn + h) * Wn + q * 4) = v;
    }
}

extern "C" void kernel_launch(void* const* d_in, const int* in_sizes, int n_in,
                              void* d_out, int out_size) {
    const float* in1 = (const float*)d_in[0];
    const float* in2 = (const float*)d_in[1];
    float* out = (float*)d_out;
    cudaFuncSetAttribute(corr1d_p3_kernel, cudaFuncAttributeMaxDynamicSharedMemorySize, DYNSMEM);
    dim3 grid(Hn, Bn);   // (96, 8)
    corr1d_p3_kernel<<<grid, NTHREADS, DYNSMEM>>>(in1, in2, out);
}

// round 9
// speedup vs baseline: 1.8481x; 1.1345x over previous
#include <cuda_runtime.h>
#include <cuda_bf16.h>
#include <cstdint>

// Correlation1D band-GEMM: k16 bf16 3-pass fp32 emulation.
// R9 = R8 with a 3-stage cp.async ring: chunk i+2 issued at iter i, required
// complete at iter i+1's bottom (wait_group 1) -> ~2 iterations of DMA cover.
// out[b,d,h,w] = (1/256)*sum_c in1[b,c,h,w]*in2pad[b,c,h,w+d-40]

#define Bn 8
#define Cn 256
#define Hn 96
#define Wn 192
#define Dn 81
#define PADn 40
#define HWn (Hn * Wn)

#define NTHREADS 384
#define KC 16
#define NCHUNK (Cn / KC)          // 16
#define BROWS 272

#define STROWF 196                // fp32 stage row floats (192 used, pad for banks)
#define STBYTES (KC * STROWF * 4) // 12544
#define STPAIR (2 * STBYTES)      // 25088 (A stage + B stage per ring slot)

#define ROWB 64                   // tileB row: [hi 16ch = 32B | lo 32B]
#define TBB (BROWS * ROWB)        // 17408

#define OFF_TB0 (3 * STPAIR)                // 75264
#define OFF_TB1 (OFF_TB0 + TBB)             // 92672
#define SMEM_USED (OFF_TB1 + TBB)           // 110080
#define DYNSMEM (SMEM_USED + 1024)

#define SWX(row, koff) ((unsigned)(koff) ^ ((((unsigned)(row) >> 1) & 3u) << 4))

static __device__ __forceinline__ uint32_t smem_u32(const void* p) {
    uint32_t a;
    asm("{ .reg .u64 t; cvta.to.shared.u64 t, %1; cvt.u32.u64 %0, t; }" : "=r"(a) : "l"(p));
    return a;
}

static __device__ __forceinline__ void cp_async16(uint32_t dst, const void* src) {
    asm volatile("cp.async.cg.shared.global [%0], [%1], 16;" :: "r"(dst), "l"(src) : "memory");
}

#define MMA_BF16(a4, A, b0, b1)                                                \
    asm volatile("mma.sync.aligned.m16n8k16.row.col.f32.bf16.bf16.f32 "        \
        "{%0,%1,%2,%3}, {%4,%5,%6,%7}, {%8,%9}, {%0,%1,%2,%3};"                \
        : "+f"((a4)[0]), "+f"((a4)[1]), "+f"((a4)[2]), "+f"((a4)[3])           \
        : "r"((A)[0]), "r"((A)[1]), "r"((A)[2]), "r"((A)[3]), "r"(b0), "r"(b1))

#define LDSM_X4(r, addr)                                                       \
    asm volatile("ldmatrix.sync.aligned.m8n8.x4.shared.b16 {%0,%1,%2,%3}, [%4];" \
        : "=r"((r)[0]), "=r"((r)[1]), "=r"((r)[2]), "=r"((r)[3]) : "r"(addr))

__global__ __launch_bounds__(NTHREADS, 2)
void corr1d_p4_kernel(const float* __restrict__ in1,
                      const float* __restrict__ in2,
                      float* __restrict__ out) {
    extern __shared__ char dsm_raw[];
    const uint32_t dsm_addr = smem_u32(dsm_raw);
    const uint32_t base_u = (dsm_addr + 1023u) & ~1023u;
    char* smp = dsm_raw + (base_u - dsm_addr);

    const int h = blockIdx.x;
    const int b = blockIdx.y;
    const int tid = threadIdx.x;
    const int wid = tid >> 5;
    const int lane = tid & 31;

    const float* a_src = in1 + (size_t)b * Cn * HWn + (size_t)h * Wn;
    const float* b_src = in2 + (size_t)b * Cn * HWn + (size_t)h * Wn;

    // ---- zero tileB pad rows (u<40, u>=232) in both buffers, once ----
    for (int t = tid; t < 2 * 80 * 4; t += NTHREADS) {
        const int buf = t / 320;
        const int r = (t % 320) / 4;
        const int j = t % 4;
        const int u = (r < 40) ? r : (232 + r - 40);
        ((uint4*)(smp + (buf ? OFF_TB1 : OFF_TB0) + u * ROWB))[j] = make_uint4(0, 0, 0, 0);
    }

    float acc[12][4];
#pragma unroll
    for (int n = 0; n < 12; ++n)
#pragma unroll
        for (int i = 0; i < 4; ++i) acc[n][i] = 0.0f;

    // convert-task constants (one task/thread): col 0..191, group g in {0,1}
    const int cv_col = tid % 192;
    const int cv_g = tid / 192;
    const int cv_u = cv_col + PADn;

    // compute constants
    const int w0 = wid * 16;
    const int b_rowoff = (lane & 7) + ((lane >> 4) & 1) * 8;
    const int b_k16 = ((lane >> 3) & 1) * 16;
    const int ad_w = w0 + (lane >> 2);
    const int ad_k = (lane & 3) * 2;

    // issue all cp.async for chunk ch into ring slot ch%3
    auto issue = [&](int ch) {
        const int c0 = ch * KC;
        const uint32_t stA = base_u + (ch % 3) * STPAIR;
        const uint32_t stB = stA + STBYTES;
#pragma unroll
        for (int j = 0; j < 4; ++j) {
            int op = tid + j * NTHREADS;        // 0..1535
            const bool isA = (op < 768);
            if (!isA) op -= 768;
            const int k = op / 48, q = op % 48;
            const uint32_t dst = (isA ? stA : stB) + k * (STROWF * 4) + q * 16;
            const float* src = (isA ? a_src : b_src) + (size_t)(c0 + k) * HWn + 4 * q;
            cp_async16(dst, src);
        }
        asm volatile("cp.async.commit_group;" ::: "memory");
    };

    uint32_t AH[4], AL[4];   // A fragments for the chunk to be computed next iter

    issue(0);
    issue(1);
    asm volatile("cp.async.wait_group 1;" ::: "memory");   // chunk 0 complete
    __syncthreads();   // stage(0) + tile pad zeros visible

    for (int i = 0; i < NCHUNK; ++i) {
        const int s3 = i % 3;
        if (i + 2 < NCHUNK) issue(i + 2);

        // ---- convert B(i): stageB[ring s3] -> tileB[i&1] ----
        {
            const char* sb = smp + s3 * STPAIR + STBYTES;
            float v[8];
#pragma unroll
            for (int j = 0; j < 8; ++j)
                v[j] = *(const float*)(sb + (8 * cv_g + j) * (STROWF * 4) + 4 * cv_col);
            unsigned hu[4], lu[4];
#pragma unroll
            for (int k = 0; k < 4; ++k) {
                __nv_bfloat162 hh = __floats2bfloat162_rn(v[2 * k], v[2 * k + 1]);
                const float r0 = v[2 * k] - __bfloat162float(hh.x);
                const float r1 = v[2 * k + 1] - __bfloat162float(hh.y);
                __nv_bfloat162 ll = __floats2bfloat162_rn(r0, r1);
                hu[k] = *(unsigned*)&hh;
                lu[k] = *(unsigned*)&ll;
            }
            char* rowp = smp + ((i & 1) ? OFF_TB1 : OFF_TB0) + cv_u * ROWB;
            *(uint4*)(rowp + SWX(cv_u, 16 * cv_g)) = make_uint4(hu[0], hu[1], hu[2], hu[3]);
            *(uint4*)(rowp + SWX(cv_u, 32 + 16 * cv_g)) = make_uint4(lu[0], lu[1], lu[2], lu[3]);
        }

        // ---- compute chunk i-1 from tileB[(i-1)&1] with A frags from last iter ----
        if (i > 0) {
            const uint32_t tb = base_u + (((i - 1) & 1) ? OFF_TB1 : OFF_TB0);
#pragma unroll
            for (int ntp = 0; ntp < 6; ++ntp) {
                const int ub = w0 + ntp * 16 + b_rowoff;
                uint32_t bh[4], bl[4];
                LDSM_X4(bh, tb + ub * ROWB + SWX(ub, b_k16));
                LDSM_X4(bl, tb + ub * ROWB + SWX(ub, 32 + b_k16));
#pragma unroll
                for (int t2 = 0; t2 < 2; ++t2) {
                    float* a4 = acc[ntp * 2 + t2];
                    MMA_BF16(a4, AH, bh[2 * t2], bh[2 * t2 + 1]);
                    MMA_BF16(a4, AH, bl[2 * t2], bl[2 * t2 + 1]);
                    MMA_BF16(a4, AL, bh[2 * t2], bh[2 * t2 + 1]);
                }
            }
        }

        // ---- build A fragments for chunk i directly from stageA[ring s3] ----
        {
            const char* sa = smp + s3 * STPAIR;
#pragma unroll
            for (int q = 0; q < 4; ++q) {
                const int ww = ad_w + (q & 1) * 8;
                const int kk = ad_k + (q >> 1) * 8;
                const float f0 = *(const float*)(sa + kk * (STROWF * 4) + 4 * ww);
                const float f1 = *(const float*)(sa + (kk + 1) * (STROWF * 4) + 4 * ww);
                __nv_bfloat162 hh = __floats2bfloat162_rn(f0, f1);
                const float r0 = f0 - __bfloat162float(hh.x);
                const float r1 = f1 - __bfloat162float(hh.y);
                __nv_bfloat162 ll = __floats2bfloat162_rn(r0, r1);
                AH[q] = *(uint32_t*)&hh;
                AL[q] = *(uint32_t*)&ll;
            }
        }

        // chunk i+1's group must be complete before iter i+1 reads it.
        // If we just issued i+2, allow it (the newest) to remain pending.
        if (i + 2 < NCHUNK) {
            asm volatile("cp.async.wait_group 1;" ::: "memory");
        } else {
            asm volatile("cp.async.wait_group 0;" ::: "memory");
        }
        __syncthreads();
    }

    // ---- tail: compute chunk NCHUNK-1 from tileB[(NCHUNK-1)&1] ----
    {
        const uint32_t tb = base_u + (((NCHUNK - 1) & 1) ? OFF_TB1 : OFF_TB0);
#pragma unroll
        for (int ntp = 0; ntp < 6; ++ntp) {
            const int ub = w0 + ntp * 16 + b_rowoff;
            uint32_t bh[4], bl[4];
            LDSM_X4(bh, tb + ub * ROWB + SWX(ub, b_k16));
            LDSM_X4(bl, tb + ub * ROWB + SWX(ub, 32 + b_k16));
#pragma unroll
            for (int t2 = 0; t2 < 2; ++t2) {
                float* a4 = acc[ntp * 2 + t2];
                MMA_BF16(a4, AH, bh[2 * t2], bh[2 * t2 + 1]);
                MMA_BF16(a4, AH, bl[2 * t2], bl[2 * t2 + 1]);
                MMA_BF16(a4, AL, bh[2 * t2], bh[2 * t2 + 1]);
            }
        }
    }
    __syncthreads();

    // ---- epilogue: band extraction into smem, then coalesced store ----
    float* outT = (float*)smp;  // [81][192] f32
    const float scale = 1.0f / (float)Cn;
    const int r_ = lane >> 2;
    const int col2 = (lane & 3) * 2;
#pragma unroll
    for (int nt = 0; nt < 12; ++nt) {
#pragma unroll
        for (int half = 0; half < 2; ++half) {
            const int mrow = r_ + half * 8;
            const int w = w0 + mrow;
#pragma unroll
            for (int e = 0; e < 2; ++e) {
                const int d = nt * 8 + col2 + e - mrow;
                if (d >= 0 && d < Dn) {
                    outT[d * Wn + w] = acc[nt][half * 2 + e] * scale;
                }
            }
        }
    }
    __syncthreads();

    for (int t = tid; t < Dn * (Wn / 4); t += NTHREADS) {
        const int d = t / (Wn / 4);
        const int q = t % (Wn / 4);
        const float4 v = ((const float4*)outT)[d * (Wn / 4) + q];
        *(float4*)(out + (((size_t)b * Dn + d) * Hn + h) * Wn + q * 4) = v;
    }
}

extern "C" void kernel_launch(void* const* d_in, const int* in_sizes, int n_in,
                              void* d_out, int out_size) {
    const float* in1 = (const float*)d_in[0];
    const float* in2 = (const float*)d_in[1];
    float* out = (float*)d_out;
    cudaFuncSetAttribute(corr1d_p4_kernel, cudaFuncAttributeMaxDynamicSharedMemorySize, DYNSMEM);
    dim3 grid(Hn, Bn);   // (96, 8)
    corr1d_p4_kernel<<<grid, NTHREADS, DYNSMEM>>>(in1, in2, out);
}